// round 13
// baseline (speedup 1.0000x reference)
#include <cuda_runtime.h>
#include <cuda_bf16.h>
#include <math.h>

#define NN 10000
#define EE 160000
#define IND 10
#define HID 256
#define TT 5
#define ODIM 3
#define MPAD 10112            // 79 * 128
#define INV_NN (1.0f / 10000.0f)

// ------------------------- static scratch (no allocation allowed) -----------
__device__ float  g_ea[EE * 12];        // normalized edge attrs (edge order)
__device__ float  g_ea2[EE * 12];       // normalized edge attrs (CSR order)
__device__ float  g_xl[NN * HID];
__device__ float  g_xr[NN * HID];
__device__ float  g_out[NN * HID];      // raw conv output (pre-BN)
__device__ int    g_deg[NN];
__device__ int    g_rowptr[NN + 1];
__device__ int    g_writeptr[NN];
__device__ int    g_src[EE];
__device__ float  g_epart[64 * 18];     // per-block edge-attr stat partials
__device__ float  g_bstats[512];        // BN stats: GAT layers (atomic target)
__device__ float  g_bstats2[512];       // BN stats: MLP layer 1
__device__ float  g_bstats3[512];       // BN stats: MLP layer 2

// bf16 split operands
__device__ __nv_bfloat16 g_Ahi[MPAD * HID];
__device__ __nv_bfloat16 g_Alo[MPAD * HID];
__device__ __nv_bfloat16 g_Bhi[12 * HID * HID];   // transposed: [slot][n][k]
__device__ __nv_bfloat16 g_Blo[12 * HID * HID];

// --------- edge-attr stat partials + zeroing of deg/bstats2/3 (first kernel)
__global__ void ea_accum_k(const float* __restrict__ ea) {
    // zero scratch for this call (later kernels consume)
    int gi = blockIdx.x * blockDim.x + threadIdx.x;   // 64*256 = 16384 threads
    if (gi < NN) g_deg[gi] = 0;
    if (gi < 512) { g_bstats2[gi] = 0.f; g_bstats3[gi] = 0.f; }

    float s[9], q[9];
#pragma unroll
    for (int c = 0; c < 9; c++) { s[c] = 0.f; q[c] = 0.f; }
    int stride = gridDim.x * blockDim.x;
    for (int r = gi; r < EE; r += stride) {
#pragma unroll
        for (int c = 0; c < 9; c++) {
            float v = ea[r * 9 + c];
            s[c] += v; q[c] += v * v;
        }
    }
#pragma unroll
    for (int c = 0; c < 9; c++) {
        for (int o = 16; o; o >>= 1) {
            s[c] += __shfl_down_sync(0xffffffffu, s[c], o);
            q[c] += __shfl_down_sync(0xffffffffu, q[c], o);
        }
    }
    __shared__ float warr[8][18];
    int lane = threadIdx.x & 31, wid = threadIdx.x >> 5;
    if (lane == 0) {
#pragma unroll
        for (int c = 0; c < 9; c++) {
            warr[wid][c] = s[c];
            warr[wid][9 + c] = q[c];
        }
    }
    __syncthreads();
    if (threadIdx.x < 18) {
        float acc = 0.f;
#pragma unroll
        for (int w = 0; w < 8; w++) acc += warr[w][threadIdx.x];
        g_epart[blockIdx.x * 18 + threadIdx.x] = acc;
    }
}

// -------- edge-attr normalization + degree histogram (count merged in) ------
__global__ void ea_norm_k(const float* __restrict__ ea, const int* __restrict__ ei) {
    __shared__ float smu[9], sinv[9];
    if (threadIdx.x < 18) {
        float acc = 0.f;
#pragma unroll 8
        for (int b = 0; b < 64; b++) acc += g_epart[b * 18 + threadIdx.x];
        if (threadIdx.x < 9) {
            // need both sum (this thread) and sumsq (thread+9): recompute pairwise
            float acc2 = 0.f;
#pragma unroll 8
            for (int b = 0; b < 64; b++) acc2 += g_epart[b * 18 + 9 + threadIdx.x];
            float mu  = acc * (1.0f / (float)EE);
            float var = acc2 * (1.0f / (float)EE) - mu * mu;
            if (var < 0.f) var = 0.f;
            smu[threadIdx.x]  = mu;
            sinv[threadIdx.x] = 1.0f / (sqrtf(var) + 1e-8f);
        }
    }
    __syncthreads();
    int r = blockIdx.x * blockDim.x + threadIdx.x;
    if (r >= EE) return;
    atomicAdd(&g_deg[ei[EE + r]], 1);     // degree histogram (deg zeroed earlier)
#pragma unroll
    for (int c = 0; c < 9; c++)
        g_ea[r * 12 + c] = (ea[r * 9 + c] - smu[c]) * sinv[c];
    g_ea[r * 12 + 9]  = 0.f;
    g_ea[r * 12 + 10] = 0.f;
    g_ea[r * 12 + 11] = 0.f;
}

// ------------------- lift fused with bf16 split (layer-0 A) -----------------
__global__ void lift_k(const float* __restrict__ x, const float* __restrict__ W,
                       const float* __restrict__ b) {
    __shared__ float sx[IND];
    int row = blockIdx.x;
    if (threadIdx.x < IND) sx[threadIdx.x] = x[row * IND + threadIdx.x];
    __syncthreads();
    int c = threadIdx.x;
    float s = b[c];
#pragma unroll
    for (int k = 0; k < IND; k++) s += sx[k] * W[k * HID + c];
    s = fmaxf(s, 0.f);
    __nv_bfloat16 h = __float2bfloat16(s);
    g_Ahi[row * HID + c] = h;
    g_Alo[row * HID + c] = __float2bfloat16(s - __bfloat162float(h));
}

// ------------------------------- CSR scan -----------------------------------
__global__ void scan_k() {
    __shared__ int wsum[32];
    __shared__ int carry_s;
    int tid = threadIdx.x;
    int lane = tid & 31, wid = tid >> 5;
    if (tid == 0) { carry_s = 0; g_rowptr[0] = 0; }
    __syncthreads();
    for (int base = 0; base < NN; base += 1024) {
        int i = base + tid;
        int v = (i < NN) ? g_deg[i] : 0;
        int x = v;
#pragma unroll
        for (int o = 1; o < 32; o <<= 1) {
            int t = __shfl_up_sync(0xffffffffu, x, o);
            if (lane >= o) x += t;
        }
        if (lane == 31) wsum[wid] = x;
        __syncthreads();
        if (wid == 0) {
            int y = wsum[lane];
#pragma unroll
            for (int o = 1; o < 32; o <<= 1) {
                int t = __shfl_up_sync(0xffffffffu, y, o);
                if (lane >= o) y += t;
            }
            wsum[lane] = y;
        }
        __syncthreads();
        int incl = x + (wid ? wsum[wid - 1] : 0) + carry_s;
        if (i < NN) { g_rowptr[i + 1] = incl; g_writeptr[i] = incl - v; }
        int total = wsum[31];
        __syncthreads();
        if (tid == 0) carry_s += total;
        __syncthreads();
    }
}

// ----------- scatter (CSR build) + weight split, merged into one launch -----
struct WPtrs { const float* p[12]; };

__global__ void scatter_wsplit_k(const int* __restrict__ ei, WPtrs wp) {
    if (blockIdx.x < 625) {
        int e = blockIdx.x * blockDim.x + threadIdx.x;
        if (e >= EE) return;
        int d = ei[EE + e];
        int pos = atomicAdd(&g_writeptr[d], 1);
        g_src[pos] = ei[e];
        const float4* s4 = (const float4*)(g_ea + e * 12);
        float4* t4 = (float4*)(g_ea2 + pos * 12);
        t4[0] = s4[0]; t4[1] = s4[1]; t4[2] = s4[2];
    } else {
        int idx = blockIdx.x - 625;          // 0..95
        int slot = idx >> 3;
        int ny = idx & 7;
        int n = ny * 32 + (threadIdx.x >> 3);
        int k0 = (threadIdx.x & 7) * 32;
        const float* W = wp.p[slot];
        __nv_bfloat16* dh = g_Bhi + slot * 65536 + n * 256 + k0;
        __nv_bfloat16* dl = g_Blo + slot * 65536 + n * 256 + k0;
#pragma unroll 8
        for (int k = 0; k < 32; k++) {
            float v = W[(k0 + k) * 256 + n];
            __nv_bfloat16 h = __float2bfloat16(v);
            dh[k] = h;
            dl[k] = __float2bfloat16(v - __bfloat162float(h));
        }
    }
}

// ----- A split with in-kernel BN coefs (fp32): act(BN(src)) -> bf16 hi/lo ---
__global__ void asplit_bn_k(const float* __restrict__ src, int act,
                            const float* __restrict__ gamma,
                            const float* __restrict__ beta,
                            const float* __restrict__ stats) {
    __shared__ float sscale[HID], sshift[HID];
    {
        int c = threadIdx.x;
        float mu  = stats[c] * INV_NN;
        float var = stats[256 + c] * INV_NN - mu * mu;
        if (var < 0.f) var = 0.f;
        float sc = gamma[c] * rsqrtf(var + 1e-5f);
        sscale[c] = sc;
        sshift[c] = beta[c] - mu * sc;
    }
    __syncthreads();

    int i0 = blockIdx.x * blockDim.x + threadIdx.x;   // 4 elements each
    if (i0 >= MPAD * 64) return;
    int row = i0 >> 6;
    int col = (i0 & 63) << 2;
    float4 v = make_float4(0.f, 0.f, 0.f, 0.f);
    if (row < NN) {
        v = *(const float4*)(src + row * 256 + col);
        float4 sc = *(const float4*)(sscale + col);
        float4 sh = *(const float4*)(sshift + col);
        v.x = v.x * sc.x + sh.x;
        v.y = v.y * sc.y + sh.y;
        v.z = v.z * sc.z + sh.z;
        v.w = v.w * sc.w + sh.w;
        if (act == 1) {
            v.x = v.x > 0.f ? v.x : expm1f(v.x);
            v.y = v.y > 0.f ? v.y : expm1f(v.y);
            v.z = v.z > 0.f ? v.z : expm1f(v.z);
            v.w = v.w > 0.f ? v.w : expm1f(v.w);
        } else {
            v.x = fmaxf(v.x, 0.f); v.y = fmaxf(v.y, 0.f);
            v.z = fmaxf(v.z, 0.f); v.w = fmaxf(v.w, 0.f);
        }
    }
    __nv_bfloat162 h0, h1, l0, l1;
    h0.x = __float2bfloat16(v.x); h0.y = __float2bfloat16(v.y);
    h1.x = __float2bfloat16(v.z); h1.y = __float2bfloat16(v.w);
    l0.x = __float2bfloat16(v.x - __bfloat162float(h0.x));
    l0.y = __float2bfloat16(v.y - __bfloat162float(h0.y));
    l1.x = __float2bfloat16(v.z - __bfloat162float(h1.x));
    l1.y = __float2bfloat16(v.w - __bfloat162float(h1.y));
    uint2 uh, ul;
    uh.x = *(unsigned*)&h0; uh.y = *(unsigned*)&h1;
    ul.x = *(unsigned*)&l0; ul.y = *(unsigned*)&l1;
    ((uint2*)g_Ahi)[i0] = uh;
    ((uint2*)g_Alo)[i0] = ul;
}

// ---------------- tensor-core GEMM: C = A @ W + bias (bf16 split) -----------
// Block (0,0,0) resets g_bstats for the next gat_edge producer.
// Optional `stats` output: epilogue accumulates per-channel sum/sumsq (MLP BN).
__device__ __forceinline__ void mma_bf16(float* c,
    unsigned a0, unsigned a1, unsigned a2, unsigned a3,
    unsigned b0, unsigned b1) {
    asm volatile(
        "mma.sync.aligned.m16n8k16.row.col.f32.bf16.bf16.f32 "
        "{%0,%1,%2,%3}, {%4,%5,%6,%7}, {%8,%9}, {%0,%1,%2,%3};\n"
        : "+f"(c[0]), "+f"(c[1]), "+f"(c[2]), "+f"(c[3])
        : "r"(a0), "r"(a1), "r"(a2), "r"(a3), "r"(b0), "r"(b1));
}

__global__ void __launch_bounds__(256, 2)
mma_gemm_k(int slot0, const float* __restrict__ bias0, float* __restrict__ C0,
           int slot1, const float* __restrict__ bias1, float* __restrict__ C1,
           float* stats) {
    if (blockIdx.x == 0 && blockIdx.y == 0 && blockIdx.z == 0) {
        g_bstats[threadIdx.x] = 0.f;
        g_bstats[threadIdx.x + 256] = 0.f;
    }
    const int slot = blockIdx.z ? slot1 : slot0;
    const float* __restrict__ bias = blockIdx.z ? bias1 : bias0;
    float* __restrict__ C = blockIdx.z ? C1 : C0;

    __shared__ __align__(16) __nv_bfloat16 Bs_h[64][136];  // pitch 68 words
    __shared__ __align__(16) __nv_bfloat16 Bs_l[64][136];
    __shared__ float sbn[128];            // local BN partials (64 sum + 64 sq)

    sbn[threadIdx.x & 127] = 0.f;         // covered twice; harmless

    const int w = threadIdx.x >> 5;
    const int lane = threadIdx.x & 31;
    const int g = lane >> 2;
    const int t = lane & 3;
    const int mbase = blockIdx.y << 7;
    const int nb = blockIdx.x << 6;
    const int r0 = mbase + (w << 4) + g;

    const __nv_bfloat16* Bh = g_Bhi + slot * 65536;
    const __nv_bfloat16* Bl = g_Blo + slot * 65536;
    const unsigned* __restrict__ Agh = (const unsigned*)g_Ahi;
    const unsigned* __restrict__ Agl = (const unsigned*)g_Alo;

    float acc[8][4];
#pragma unroll
    for (int j = 0; j < 8; j++)
#pragma unroll
        for (int q = 0; q < 4; q++) acc[j][q] = 0.f;

    for (int kh = 0; kh < 2; kh++) {
        {
            int row = threadIdx.x >> 2;
            int q = threadIdx.x & 3;
            const uint4* sh4 = (const uint4*)(Bh + (nb + row) * 256 + kh * 128 + q * 32);
            const uint4* sl4 = (const uint4*)(Bl + (nb + row) * 256 + kh * 128 + q * 32);
            uint4* dh4 = (uint4*)(&Bs_h[row][q * 32]);
            uint4* dl4 = (uint4*)(&Bs_l[row][q * 32]);
#pragma unroll
            for (int u = 0; u < 4; u++) { dh4[u] = sh4[u]; dl4[u] = sl4[u]; }
        }
        __syncthreads();

        const unsigned* bsh = (const unsigned*)Bs_h;
        const unsigned* bsl = (const unsigned*)Bs_l;
#pragma unroll
        for (int s = 0; s < 8; s++) {
            int kw = kh * 64 + s * 8 + t;
            unsigned ah0 = Agh[r0 * 128 + kw];
            unsigned ah1 = Agh[(r0 + 8) * 128 + kw];
            unsigned ah2 = Agh[r0 * 128 + kw + 4];
            unsigned ah3 = Agh[(r0 + 8) * 128 + kw + 4];
            unsigned al0 = Agl[r0 * 128 + kw];
            unsigned al1 = Agl[(r0 + 8) * 128 + kw];
            unsigned al2 = Agl[r0 * 128 + kw + 4];
            unsigned al3 = Agl[(r0 + 8) * 128 + kw + 4];
#pragma unroll
            for (int j = 0; j < 8; j++) {
                int n = (j << 3) + g;
                int wi = n * 68 + (s << 3) + t;
                unsigned bh0 = bsh[wi], bh1 = bsh[wi + 4];
                unsigned bl0 = bsl[wi], bl1 = bsl[wi + 4];
                mma_bf16(acc[j], ah0, ah1, ah2, ah3, bh0, bh1);
                mma_bf16(acc[j], al0, al1, al2, al3, bh0, bh1);
                mma_bf16(acc[j], ah0, ah1, ah2, ah3, bl0, bl1);
            }
        }
        __syncthreads();
    }

#pragma unroll
    for (int j = 0; j < 8; j++) {
        int c = nb + (j << 3) + (t << 1);
        float2 bv = *(const float2*)(bias + c);
        int lc = (j << 3) + (t << 1);
        if (r0 < NN) {
            float2 o; o.x = acc[j][0] + bv.x; o.y = acc[j][1] + bv.y;
            *(float2*)(C + r0 * 256 + c) = o;
            if (stats) {
                atomicAdd(&sbn[lc + 0], o.x);
                atomicAdd(&sbn[lc + 1], o.y);
                atomicAdd(&sbn[64 + lc + 0], o.x * o.x);
                atomicAdd(&sbn[64 + lc + 1], o.y * o.y);
            }
        }
        if (r0 + 8 < NN) {
            float2 o; o.x = acc[j][2] + bv.x; o.y = acc[j][3] + bv.y;
            *(float2*)(C + (r0 + 8) * 256 + c) = o;
            if (stats) {
                atomicAdd(&sbn[lc + 0], o.x);
                atomicAdd(&sbn[lc + 1], o.y);
                atomicAdd(&sbn[64 + lc + 0], o.x * o.x);
                atomicAdd(&sbn[64 + lc + 1], o.y * o.y);
            }
        }
    }
    if (stats) {
        __syncthreads();
        if (threadIdx.x < 64)
            atomicAdd(&stats[nb + threadIdx.x], sbn[threadIdx.x]);
        else if (threadIdx.x < 128)
            atomicAdd(&stats[256 + nb + (threadIdx.x - 64)], sbn[threadIdx.x]);
    }
}

// --------- GATv2 edge pass: plain-exp softmax + fused BN-stat atomics -------
__global__ void gat_edge_k(const float* __restrict__ xl, const float* __restrict__ xr,
                           const float* __restrict__ We_t, const float* __restrict__ att_t,
                           const float* __restrict__ cbias, float* __restrict__ out) {
    __shared__ float sbn[512];
    sbn[threadIdx.x] = 0.f;
    sbn[threadIdx.x + 256] = 0.f;
    __syncthreads();

    int gw = (blockIdx.x * blockDim.x + threadIdx.x) >> 5;
    int lane = threadIdx.x & 31;
    int node = gw >> 1;
    int cb = ((gw & 1) << 7) + (lane << 2);
    bool active = (gw < NN * 2);

    float4 o = make_float4(0.f, 0.f, 0.f, 0.f);
    if (active) {
        float4 wk[9];
#pragma unroll
        for (int k = 0; k < 9; k++) wk[k] = *(const float4*)(We_t + k * HID + cb);
        float4 xr4 = *(const float4*)(xr + node * HID + cb);
        float4 at4 = *(const float4*)(att_t + cb);

        int beg = g_rowptr[node], end = g_rowptr[node + 1];
        float denom = 0.f;
        float a0 = 0.f, a1 = 0.f, a2 = 0.f, a3 = 0.f;

        float4 e0, e1, e2, x4;
        if (beg < end) {
            int s = g_src[beg];
            const float4* eap = (const float4*)(g_ea2 + beg * 12);
            e0 = eap[0]; e1 = eap[1]; e2 = eap[2];
            x4 = *(const float4*)(xl + s * HID + cb);
        }

        for (int pos = beg; pos < end; pos++) {
            float4 ce0 = e0, ce1 = e1, ce2 = e2, cx4 = x4;
            if (pos + 1 < end) {
                int sn = g_src[pos + 1];
                const float4* eap = (const float4*)(g_ea2 + (pos + 1) * 12);
                e0 = eap[0]; e1 = eap[1]; e2 = eap[2];
                x4 = *(const float4*)(xl + sn * HID + cb);
            }

            float xe0 = ce0.x*wk[0].x + ce0.y*wk[1].x + ce0.z*wk[2].x + ce0.w*wk[3].x
                      + ce1.x*wk[4].x + ce1.y*wk[5].x + ce1.z*wk[6].x + ce1.w*wk[7].x + ce2.x*wk[8].x;
            float xe1 = ce0.x*wk[0].y + ce0.y*wk[1].y + ce0.z*wk[2].y + ce0.w*wk[3].y
                      + ce1.x*wk[4].y + ce1.y*wk[5].y + ce1.z*wk[6].y + ce1.w*wk[7].y + ce2.x*wk[8].y;
            float xe2 = ce0.x*wk[0].z + ce0.y*wk[1].z + ce0.z*wk[2].z + ce0.w*wk[3].z
                      + ce1.x*wk[4].z + ce1.y*wk[5].z + ce1.z*wk[6].z + ce1.w*wk[7].z + ce2.x*wk[8].z;
            float xe3 = ce0.x*wk[0].w + ce0.y*wk[1].w + ce0.z*wk[2].w + ce0.w*wk[3].w
                      + ce1.x*wk[4].w + ce1.y*wk[5].w + ce1.z*wk[6].w + ce1.w*wk[7].w + ce2.x*wk[8].w;

            float v0 = cx4.x + xr4.x + xe0; v0 = v0 > 0.f ? v0 : 0.2f * v0;
            float v1 = cx4.y + xr4.y + xe1; v1 = v1 > 0.f ? v1 : 0.2f * v1;
            float v2 = cx4.z + xr4.z + xe2; v2 = v2 > 0.f ? v2 : 0.2f * v2;
            float v3 = cx4.w + xr4.w + xe3; v3 = v3 > 0.f ? v3 : 0.2f * v3;

            float part = v0 * at4.x + v1 * at4.y + v2 * at4.z + v3 * at4.w;
            part += __shfl_xor_sync(0xffffffffu, part, 1);
            part += __shfl_xor_sync(0xffffffffu, part, 2);
            part += __shfl_xor_sync(0xffffffffu, part, 4);

            float z = __expf(part);
            denom += z;
            a0 += z * cx4.x;
            a1 += z * cx4.y;
            a2 += z * cx4.z;
            a3 += z * cx4.w;
        }
        float inv = 1.f / (denom + 1e-16f);
        o.x = a0 * inv + cbias[cb + 0];
        o.y = a1 * inv + cbias[cb + 1];
        o.z = a2 * inv + cbias[cb + 2];
        o.w = a3 * inv + cbias[cb + 3];
        *(float4*)(out + node * HID + cb) = o;

        atomicAdd(&sbn[cb + 0], o.x);             atomicAdd(&sbn[cb + 1], o.y);
        atomicAdd(&sbn[cb + 2], o.z);             atomicAdd(&sbn[cb + 3], o.w);
        atomicAdd(&sbn[256 + cb + 0], o.x * o.x); atomicAdd(&sbn[256 + cb + 1], o.y * o.y);
        atomicAdd(&sbn[256 + cb + 2], o.z * o.z); atomicAdd(&sbn[256 + cb + 3], o.w * o.w);
    }
    __syncthreads();
    atomicAdd(&g_bstats[threadIdx.x], sbn[threadIdx.x]);
    atomicAdd(&g_bstats[threadIdx.x + 256], sbn[threadIdx.x + 256]);
}

// -------- final 256x3 projection (BN coefs computed in-kernel, fp32) --------
__global__ void proj3_k(const float* __restrict__ h, const float* __restrict__ W,
                        const float* __restrict__ b,
                        const float* __restrict__ gamma, const float* __restrict__ beta,
                        float* __restrict__ out) {
    __shared__ float sscale[HID], sshift[HID];
    {
        int c = threadIdx.x;
        float mu  = g_bstats3[c] * INV_NN;
        float var = g_bstats3[256 + c] * INV_NN - mu * mu;
        if (var < 0.f) var = 0.f;
        float sc = gamma[c] * rsqrtf(var + 1e-5f);
        sscale[c] = sc;
        sshift[c] = beta[c] - mu * sc;
    }
    __syncthreads();

    int gw = (blockIdx.x * blockDim.x + threadIdx.x) >> 5;
    int lane = threadIdx.x & 31;
    if (gw >= NN) return;
    int cbase = lane * 8;
    const float* hp = h + gw * HID + cbase;
    float4 h0 = *(const float4*)hp;
    float4 h1 = *(const float4*)(hp + 4);
    float4 s0_ = *(const float4*)(sscale + cbase);
    float4 s1_ = *(const float4*)(sscale + cbase + 4);
    float4 f0_ = *(const float4*)(sshift + cbase);
    float4 f1_ = *(const float4*)(sshift + cbase + 4);
    float hv[8];
    hv[0] = fmaxf(h0.x * s0_.x + f0_.x, 0.f);
    hv[1] = fmaxf(h0.y * s0_.y + f0_.y, 0.f);
    hv[2] = fmaxf(h0.z * s0_.z + f0_.z, 0.f);
    hv[3] = fmaxf(h0.w * s0_.w + f0_.w, 0.f);
    hv[4] = fmaxf(h1.x * s1_.x + f1_.x, 0.f);
    hv[5] = fmaxf(h1.y * s1_.y + f1_.y, 0.f);
    hv[6] = fmaxf(h1.z * s1_.z + f1_.z, 0.f);
    hv[7] = fmaxf(h1.w * s1_.w + f1_.w, 0.f);
    float s0 = 0.f, s1 = 0.f, s2 = 0.f;
#pragma unroll
    for (int j = 0; j < 8; j++) {
        int c = cbase + j;
        s0 += hv[j] * W[c * 3 + 0];
        s1 += hv[j] * W[c * 3 + 1];
        s2 += hv[j] * W[c * 3 + 2];
    }
    for (int o = 16; o; o >>= 1) {
        s0 += __shfl_down_sync(0xffffffffu, s0, o);
        s1 += __shfl_down_sync(0xffffffffu, s1, o);
        s2 += __shfl_down_sync(0xffffffffu, s2, o);
    }
    if (lane == 0) {
        out[gw * 3 + 0] = s0 + b[0];
        out[gw * 3 + 1] = s1 + b[1];
        out[gw * 3 + 2] = s2 + b[2];
    }
}

// --------------------------------- launcher ---------------------------------
extern "C" void kernel_launch(void* const* d_in, const int* in_sizes, int n_in,
                              void* d_out, int out_size) {
    const float* x         = (const float*)d_in[0];
    const float* edge_attr = (const float*)d_in[1];
    const int*   edge_idx  = (const int*)  d_in[2];
    const float* lift_W    = (const float*)d_in[3];
    const float* lift_b    = (const float*)d_in[4];
    const float* Wl        = (const float*)d_in[5];
    const float* bl        = (const float*)d_in[6];
    const float* Wr        = (const float*)d_in[7];
    const float* br        = (const float*)d_in[8];
    const float* We        = (const float*)d_in[9];
    const float* att       = (const float*)d_in[10];
    const float* conv_bias = (const float*)d_in[11];
    const float* bn_gamma  = (const float*)d_in[12];
    const float* bn_beta   = (const float*)d_in[13];
    const float* p1_W      = (const float*)d_in[14];
    const float* p1_b      = (const float*)d_in[15];
    const float* pbn1_g    = (const float*)d_in[16];
    const float* pbn1_b    = (const float*)d_in[17];
    const float* p2_W      = (const float*)d_in[18];
    const float* p2_b      = (const float*)d_in[19];
    const float* pbn2_g    = (const float*)d_in[20];
    const float* pbn2_b    = (const float*)d_in[21];
    const float* p3_W      = (const float*)d_in[22];
    const float* p3_b      = (const float*)d_in[23];
    float* outp = (float*)d_out;

    float* p_xl  = nullptr;  cudaGetSymbolAddress((void**)&p_xl,  g_xl);
    float* p_xr  = nullptr;  cudaGetSymbolAddress((void**)&p_xr,  g_xr);
    float* p_out = nullptr;  cudaGetSymbolAddress((void**)&p_out, g_out);
    float* p_bs  = nullptr;  cudaGetSymbolAddress((void**)&p_bs,  g_bstats);
    float* p_bs2 = nullptr;  cudaGetSymbolAddress((void**)&p_bs2, g_bstats2);
    float* p_bs3 = nullptr;  cudaGetSymbolAddress((void**)&p_bs3, g_bstats3);

    const int EB = (EE + 255) / 256;              // 625
    dim3 ggrid2(4, MPAD / 128, 2);                // dual GEMM (Wl + Wr)
    dim3 ggrid1(4, MPAD / 128, 1);                // single GEMM
    const int ASB = (MPAD * 64 + 255) / 256;      // asplit blocks

    ea_accum_k<<<64, 256>>>(edge_attr);           // also zeroes deg/bstats2/3
    ea_norm_k<<<EB, 256>>>(edge_attr, edge_idx);  // also degree histogram

    lift_k<<<NN, 256>>>(x, lift_W, lift_b);       // writes Ahi/Alo directly

    scan_k<<<1, 1024>>>();

    WPtrs wp;
    for (int t = 0; t < TT; t++) {
        wp.p[t]     = Wl + t * HID * HID;
        wp.p[5 + t] = Wr + t * HID * HID;
    }
    wp.p[10] = p1_W;
    wp.p[11] = p2_W;
    scatter_wsplit_k<<<625 + 96, 256>>>(edge_idx, wp);

    for (int t = 0; t < TT; t++) {
        if (t > 0)
            asplit_bn_k<<<ASB, 256>>>(p_out, 1,
                                      bn_gamma + (t - 1) * HID, bn_beta + (t - 1) * HID,
                                      p_bs);
        mma_gemm_k<<<ggrid2, 256>>>(t, bl + t * HID, p_xl,
                                    5 + t, br + t * HID, p_xr, nullptr);
        gat_edge_k<<<2500, 256>>>(
            p_xl, p_xr, We + t * 9 * HID, att + t * HID, conv_bias + t * HID, p_out);
    }

    // projection MLP (stats produced in GEMM epilogues)
    asplit_bn_k<<<ASB, 256>>>(p_out, 1, bn_gamma + 4 * HID, bn_beta + 4 * HID, p_bs);
    mma_gemm_k<<<ggrid1, 256>>>(10, p1_b, p_xl, 10, p1_b, p_xl, p_bs2);

    asplit_bn_k<<<ASB, 256>>>(p_xl, 2, pbn1_g, pbn1_b, p_bs2);
    mma_gemm_k<<<ggrid1, 256>>>(11, p2_b, p_xr, 11, p2_b, p_xr, p_bs3);

    proj3_k<<<(NN * 32 + 255) / 256, 256>>>(p_xr, p3_W, p3_b, pbn2_g, pbn2_b, outp);
}

// round 14
// speedup vs baseline: 1.1778x; 1.1778x over previous
#include <cuda_runtime.h>
#include <cuda_bf16.h>
#include <math.h>

#define NN 10000
#define EE 160000
#define IND 10
#define HID 256
#define TT 5
#define ODIM 3
#define MPAD 10112            // 79 * 128
#define INV_NN (1.0f / 10000.0f)

// ------------------------- static scratch (no allocation allowed) -----------
__device__ float  g_ea[EE * 12];        // normalized edge attrs (edge order)
__device__ float  g_ea2[EE * 12];       // normalized edge attrs (CSR order)
__device__ float  g_xl[NN * HID];
__device__ float  g_xr[NN * HID];
__device__ float  g_out[NN * HID];      // raw conv output (pre-BN)
__device__ int    g_deg[NN];
__device__ int    g_rowptr[NN + 1];
__device__ int    g_writeptr[NN];
__device__ int    g_src[EE];
__device__ float  g_epart[64 * 18];     // per-block edge-attr stat partials
__device__ float  g_bstats[512];        // fp32 BN stats (atomic target)

// bf16 split operands
__device__ __nv_bfloat16 g_Ahi[MPAD * HID];
__device__ __nv_bfloat16 g_Alo[MPAD * HID];
__device__ __nv_bfloat16 g_Bhi[12 * HID * HID];   // transposed: [slot][n][k]
__device__ __nv_bfloat16 g_Blo[12 * HID * HID];

// ---- edge-attr stat partials (no atomics) + zeroing of g_deg (first kernel)
__global__ void ea_accum_k(const float* __restrict__ ea) {
    int gi = blockIdx.x * blockDim.x + threadIdx.x;   // 16384 threads
    if (gi < NN) g_deg[gi] = 0;

    float s[9], q[9];
#pragma unroll
    for (int c = 0; c < 9; c++) { s[c] = 0.f; q[c] = 0.f; }
    int stride = gridDim.x * blockDim.x;
    for (int r = gi; r < EE; r += stride) {
#pragma unroll
        for (int c = 0; c < 9; c++) {
            float v = ea[r * 9 + c];
            s[c] += v; q[c] += v * v;
        }
    }
#pragma unroll
    for (int c = 0; c < 9; c++) {
        for (int o = 16; o; o >>= 1) {
            s[c] += __shfl_down_sync(0xffffffffu, s[c], o);
            q[c] += __shfl_down_sync(0xffffffffu, q[c], o);
        }
    }
    __shared__ float warr[8][18];
    int lane = threadIdx.x & 31, wid = threadIdx.x >> 5;
    if (lane == 0) {
#pragma unroll
        for (int c = 0; c < 9; c++) {
            warr[wid][c] = s[c];
            warr[wid][9 + c] = q[c];
        }
    }
    __syncthreads();
    if (threadIdx.x < 18) {
        float acc = 0.f;
#pragma unroll
        for (int w = 0; w < 8; w++) acc += warr[w][threadIdx.x];
        g_epart[blockIdx.x * 18 + threadIdx.x] = acc;
    }
}

// -------- edge-attr normalization + degree histogram (count merged in) ------
__global__ void ea_norm_k(const float* __restrict__ ea, const int* __restrict__ ei) {
    __shared__ float smu[9], sinv[9];
    if (threadIdx.x < 9) {
        float acc = 0.f, acc2 = 0.f;
#pragma unroll 8
        for (int b = 0; b < 64; b++) {
            acc  += g_epart[b * 18 + threadIdx.x];
            acc2 += g_epart[b * 18 + 9 + threadIdx.x];
        }
        float mu  = acc * (1.0f / (float)EE);
        float var = acc2 * (1.0f / (float)EE) - mu * mu;
        if (var < 0.f) var = 0.f;
        smu[threadIdx.x]  = mu;
        sinv[threadIdx.x] = 1.0f / (sqrtf(var) + 1e-8f);
    }
    __syncthreads();
    int r = blockIdx.x * blockDim.x + threadIdx.x;
    if (r >= EE) return;
    atomicAdd(&g_deg[ei[EE + r]], 1);     // degree histogram (deg zeroed earlier)
#pragma unroll
    for (int c = 0; c < 9; c++)
        g_ea[r * 12 + c] = (ea[r * 9 + c] - smu[c]) * sinv[c];
    g_ea[r * 12 + 9]  = 0.f;
    g_ea[r * 12 + 10] = 0.f;
    g_ea[r * 12 + 11] = 0.f;
}

// ------------------- lift fused with bf16 split (layer-0 A) -----------------
__global__ void lift_k(const float* __restrict__ x, const float* __restrict__ W,
                       const float* __restrict__ b) {
    __shared__ float sx[IND];
    int row = blockIdx.x;
    if (threadIdx.x < IND) sx[threadIdx.x] = x[row * IND + threadIdx.x];
    __syncthreads();
    int c = threadIdx.x;
    float s = b[c];
#pragma unroll
    for (int k = 0; k < IND; k++) s += sx[k] * W[k * HID + c];
    s = fmaxf(s, 0.f);
    __nv_bfloat16 h = __float2bfloat16(s);
    g_Ahi[row * HID + c] = h;
    g_Alo[row * HID + c] = __float2bfloat16(s - __bfloat162float(h));
}

// ------------------------------- CSR scan -----------------------------------
__global__ void scan_k() {
    __shared__ int wsum[32];
    __shared__ int carry_s;
    int tid = threadIdx.x;
    int lane = tid & 31, wid = tid >> 5;
    if (tid == 0) { carry_s = 0; g_rowptr[0] = 0; }
    __syncthreads();
    for (int base = 0; base < NN; base += 1024) {
        int i = base + tid;
        int v = (i < NN) ? g_deg[i] : 0;
        int x = v;
#pragma unroll
        for (int o = 1; o < 32; o <<= 1) {
            int t = __shfl_up_sync(0xffffffffu, x, o);
            if (lane >= o) x += t;
        }
        if (lane == 31) wsum[wid] = x;
        __syncthreads();
        if (wid == 0) {
            int y = wsum[lane];
#pragma unroll
            for (int o = 1; o < 32; o <<= 1) {
                int t = __shfl_up_sync(0xffffffffu, y, o);
                if (lane >= o) y += t;
            }
            wsum[lane] = y;
        }
        __syncthreads();
        int incl = x + (wid ? wsum[wid - 1] : 0) + carry_s;
        if (i < NN) { g_rowptr[i + 1] = incl; g_writeptr[i] = incl - v; }
        int total = wsum[31];
        __syncthreads();
        if (tid == 0) carry_s += total;
        __syncthreads();
    }
}

// ----------- scatter (CSR build) + weight split, merged into one launch -----
struct WPtrs { const float* p[12]; };

__global__ void scatter_wsplit_k(const int* __restrict__ ei, WPtrs wp) {
    if (blockIdx.x < 625) {
        int e = blockIdx.x * blockDim.x + threadIdx.x;
        if (e >= EE) return;
        int d = ei[EE + e];
        int pos = atomicAdd(&g_writeptr[d], 1);
        g_src[pos] = ei[e];
        const float4* s4 = (const float4*)(g_ea + e * 12);
        float4* t4 = (float4*)(g_ea2 + pos * 12);
        t4[0] = s4[0]; t4[1] = s4[1]; t4[2] = s4[2];
    } else {
        int idx = blockIdx.x - 625;          // 0..95
        int slot = idx >> 3;
        int ny = idx & 7;
        int n = ny * 32 + (threadIdx.x >> 3);
        int k0 = (threadIdx.x & 7) * 32;
        const float* W = wp.p[slot];
        __nv_bfloat16* dh = g_Bhi + slot * 65536 + n * 256 + k0;
        __nv_bfloat16* dl = g_Blo + slot * 65536 + n * 256 + k0;
#pragma unroll 8
        for (int k = 0; k < 32; k++) {
            float v = W[(k0 + k) * 256 + n];
            __nv_bfloat16 h = __float2bfloat16(v);
            dh[k] = h;
            dl[k] = __float2bfloat16(v - __bfloat162float(h));
        }
    }
}

// ----- A split with in-kernel BN coefs (fp32): act(BN(src)) -> bf16 hi/lo ---
__global__ void asplit_bn_k(const float* __restrict__ src, int act,
                            const float* __restrict__ gamma,
                            const float* __restrict__ beta) {
    __shared__ float sscale[HID], sshift[HID];
    {
        int c = threadIdx.x;
        float mu  = g_bstats[c] * INV_NN;
        float var = g_bstats[256 + c] * INV_NN - mu * mu;
        if (var < 0.f) var = 0.f;
        float sc = gamma[c] * rsqrtf(var + 1e-5f);
        sscale[c] = sc;
        sshift[c] = beta[c] - mu * sc;
    }
    __syncthreads();

    int i0 = blockIdx.x * blockDim.x + threadIdx.x;   // 4 elements each
    if (i0 >= MPAD * 64) return;
    int row = i0 >> 6;
    int col = (i0 & 63) << 2;
    float4 v = make_float4(0.f, 0.f, 0.f, 0.f);
    if (row < NN) {
        v = *(const float4*)(src + row * 256 + col);
        float4 sc = *(const float4*)(sscale + col);
        float4 sh = *(const float4*)(sshift + col);
        v.x = v.x * sc.x + sh.x;
        v.y = v.y * sc.y + sh.y;
        v.z = v.z * sc.z + sh.z;
        v.w = v.w * sc.w + sh.w;
        if (act == 1) {
            v.x = v.x > 0.f ? v.x : expm1f(v.x);
            v.y = v.y > 0.f ? v.y : expm1f(v.y);
            v.z = v.z > 0.f ? v.z : expm1f(v.z);
            v.w = v.w > 0.f ? v.w : expm1f(v.w);
        } else {
            v.x = fmaxf(v.x, 0.f); v.y = fmaxf(v.y, 0.f);
            v.z = fmaxf(v.z, 0.f); v.w = fmaxf(v.w, 0.f);
        }
    }
    __nv_bfloat162 h0, h1, l0, l1;
    h0.x = __float2bfloat16(v.x); h0.y = __float2bfloat16(v.y);
    h1.x = __float2bfloat16(v.z); h1.y = __float2bfloat16(v.w);
    l0.x = __float2bfloat16(v.x - __bfloat162float(h0.x));
    l0.y = __float2bfloat16(v.y - __bfloat162float(h0.y));
    l1.x = __float2bfloat16(v.z - __bfloat162float(h1.x));
    l1.y = __float2bfloat16(v.w - __bfloat162float(h1.y));
    uint2 uh, ul;
    uh.x = *(unsigned*)&h0; uh.y = *(unsigned*)&h1;
    ul.x = *(unsigned*)&l0; ul.y = *(unsigned*)&l1;
    ((uint2*)g_Ahi)[i0] = uh;
    ((uint2*)g_Alo)[i0] = ul;
}

// ---------------- tensor-core GEMM (round-12 version, untouched) ------------
// Block (0,0,0) resets g_bstats for the next stats producer.
__device__ __forceinline__ void mma_bf16(float* c,
    unsigned a0, unsigned a1, unsigned a2, unsigned a3,
    unsigned b0, unsigned b1) {
    asm volatile(
        "mma.sync.aligned.m16n8k16.row.col.f32.bf16.bf16.f32 "
        "{%0,%1,%2,%3}, {%4,%5,%6,%7}, {%8,%9}, {%0,%1,%2,%3};\n"
        : "+f"(c[0]), "+f"(c[1]), "+f"(c[2]), "+f"(c[3])
        : "r"(a0), "r"(a1), "r"(a2), "r"(a3), "r"(b0), "r"(b1));
}

__global__ void __launch_bounds__(256, 2)
mma_gemm_k(int slot0, const float* __restrict__ bias0, float* __restrict__ C0,
           int slot1, const float* __restrict__ bias1, float* __restrict__ C1) {
    if (blockIdx.x == 0 && blockIdx.y == 0 && blockIdx.z == 0) {
        g_bstats[threadIdx.x] = 0.f;
        g_bstats[threadIdx.x + 256] = 0.f;
    }
    const int slot = blockIdx.z ? slot1 : slot0;
    const float* __restrict__ bias = blockIdx.z ? bias1 : bias0;
    float* __restrict__ C = blockIdx.z ? C1 : C0;

    __shared__ __align__(16) __nv_bfloat16 Bs_h[64][136];  // pitch 68 words
    __shared__ __align__(16) __nv_bfloat16 Bs_l[64][136];

    const int w = threadIdx.x >> 5;
    const int lane = threadIdx.x & 31;
    const int g = lane >> 2;
    const int t = lane & 3;
    const int mbase = blockIdx.y << 7;
    const int nb = blockIdx.x << 6;
    const int r0 = mbase + (w << 4) + g;

    const __nv_bfloat16* Bh = g_Bhi + slot * 65536;
    const __nv_bfloat16* Bl = g_Blo + slot * 65536;
    const unsigned* __restrict__ Agh = (const unsigned*)g_Ahi;
    const unsigned* __restrict__ Agl = (const unsigned*)g_Alo;

    float acc[8][4];
#pragma unroll
    for (int j = 0; j < 8; j++)
#pragma unroll
        for (int q = 0; q < 4; q++) acc[j][q] = 0.f;

    for (int kh = 0; kh < 2; kh++) {
        {
            int row = threadIdx.x >> 2;
            int q = threadIdx.x & 3;
            const uint4* sh4 = (const uint4*)(Bh + (nb + row) * 256 + kh * 128 + q * 32);
            const uint4* sl4 = (const uint4*)(Bl + (nb + row) * 256 + kh * 128 + q * 32);
            uint4* dh4 = (uint4*)(&Bs_h[row][q * 32]);
            uint4* dl4 = (uint4*)(&Bs_l[row][q * 32]);
#pragma unroll
            for (int u = 0; u < 4; u++) { dh4[u] = sh4[u]; dl4[u] = sl4[u]; }
        }
        __syncthreads();

        const unsigned* bsh = (const unsigned*)Bs_h;
        const unsigned* bsl = (const unsigned*)Bs_l;
#pragma unroll
        for (int s = 0; s < 8; s++) {
            int kw = kh * 64 + s * 8 + t;
            unsigned ah0 = Agh[r0 * 128 + kw];
            unsigned ah1 = Agh[(r0 + 8) * 128 + kw];
            unsigned ah2 = Agh[r0 * 128 + kw + 4];
            unsigned ah3 = Agh[(r0 + 8) * 128 + kw + 4];
            unsigned al0 = Agl[r0 * 128 + kw];
            unsigned al1 = Agl[(r0 + 8) * 128 + kw];
            unsigned al2 = Agl[r0 * 128 + kw + 4];
            unsigned al3 = Agl[(r0 + 8) * 128 + kw + 4];
#pragma unroll
            for (int j = 0; j < 8; j++) {
                int n = (j << 3) + g;
                int wi = n * 68 + (s << 3) + t;
                unsigned bh0 = bsh[wi], bh1 = bsh[wi + 4];
                unsigned bl0 = bsl[wi], bl1 = bsl[wi + 4];
                mma_bf16(acc[j], ah0, ah1, ah2, ah3, bh0, bh1);
                mma_bf16(acc[j], al0, al1, al2, al3, bh0, bh1);
                mma_bf16(acc[j], ah0, ah1, ah2, ah3, bl0, bl1);
            }
        }
        __syncthreads();
    }

#pragma unroll
    for (int j = 0; j < 8; j++) {
        int c = nb + (j << 3) + (t << 1);
        float2 bv = *(const float2*)(bias + c);
        if (r0 < NN) {
            float2 o; o.x = acc[j][0] + bv.x; o.y = acc[j][1] + bv.y;
            *(float2*)(C + r0 * 256 + c) = o;
        }
        if (r0 + 8 < NN) {
            float2 o; o.x = acc[j][2] + bv.x; o.y = acc[j][3] + bv.y;
            *(float2*)(C + (r0 + 8) * 256 + c) = o;
        }
    }
}

// --------- GATv2 edge pass: plain-exp softmax + fused BN-stat atomics -------
__global__ void gat_edge_k(const float* __restrict__ xl, const float* __restrict__ xr,
                           const float* __restrict__ We_t, const float* __restrict__ att_t,
                           const float* __restrict__ cbias, float* __restrict__ out) {
    __shared__ float sbn[512];
    sbn[threadIdx.x] = 0.f;
    sbn[threadIdx.x + 256] = 0.f;
    __syncthreads();

    int gw = (blockIdx.x * blockDim.x + threadIdx.x) >> 5;
    int lane = threadIdx.x & 31;
    int node = gw >> 1;
    int cb = ((gw & 1) << 7) + (lane << 2);
    bool active = (gw < NN * 2);

    float4 o = make_float4(0.f, 0.f, 0.f, 0.f);
    if (active) {
        float4 wk[9];
#pragma unroll
        for (int k = 0; k < 9; k++) wk[k] = *(const float4*)(We_t + k * HID + cb);
        float4 xr4 = *(const float4*)(xr + node * HID + cb);
        float4 at4 = *(const float4*)(att_t + cb);

        int beg = g_rowptr[node], end = g_rowptr[node + 1];
        float denom = 0.f;
        float a0 = 0.f, a1 = 0.f, a2 = 0.f, a3 = 0.f;

        float4 e0, e1, e2, x4;
        if (beg < end) {
            int s = g_src[beg];
            const float4* eap = (const float4*)(g_ea2 + beg * 12);
            e0 = eap[0]; e1 = eap[1]; e2 = eap[2];
            x4 = *(const float4*)(xl + s * HID + cb);
        }

        for (int pos = beg; pos < end; pos++) {
            float4 ce0 = e0, ce1 = e1, ce2 = e2, cx4 = x4;
            if (pos + 1 < end) {
                int sn = g_src[pos + 1];
                const float4* eap = (const float4*)(g_ea2 + (pos + 1) * 12);
                e0 = eap[0]; e1 = eap[1]; e2 = eap[2];
                x4 = *(const float4*)(xl + sn * HID + cb);
            }

            float xe0 = ce0.x*wk[0].x + ce0.y*wk[1].x + ce0.z*wk[2].x + ce0.w*wk[3].x
                      + ce1.x*wk[4].x + ce1.y*wk[5].x + ce1.z*wk[6].x + ce1.w*wk[7].x + ce2.x*wk[8].x;
            float xe1 = ce0.x*wk[0].y + ce0.y*wk[1].y + ce0.z*wk[2].y + ce0.w*wk[3].y
                      + ce1.x*wk[4].y + ce1.y*wk[5].y + ce1.z*wk[6].y + ce1.w*wk[7].y + ce2.x*wk[8].y;
            float xe2 = ce0.x*wk[0].z + ce0.y*wk[1].z + ce0.z*wk[2].z + ce0.w*wk[3].z
                      + ce1.x*wk[4].z + ce1.y*wk[5].z + ce1.z*wk[6].z + ce1.w*wk[7].z + ce2.x*wk[8].z;
            float xe3 = ce0.x*wk[0].w + ce0.y*wk[1].w + ce0.z*wk[2].w + ce0.w*wk[3].w
                      + ce1.x*wk[4].w + ce1.y*wk[5].w + ce1.z*wk[6].w + ce1.w*wk[7].w + ce2.x*wk[8].w;

            float v0 = cx4.x + xr4.x + xe0; v0 = v0 > 0.f ? v0 : 0.2f * v0;
            float v1 = cx4.y + xr4.y + xe1; v1 = v1 > 0.f ? v1 : 0.2f * v1;
            float v2 = cx4.z + xr4.z + xe2; v2 = v2 > 0.f ? v2 : 0.2f * v2;
            float v3 = cx4.w + xr4.w + xe3; v3 = v3 > 0.f ? v3 : 0.2f * v3;

            float part = v0 * at4.x + v1 * at4.y + v2 * at4.z + v3 * at4.w;
            part += __shfl_xor_sync(0xffffffffu, part, 1);
            part += __shfl_xor_sync(0xffffffffu, part, 2);
            part += __shfl_xor_sync(0xffffffffu, part, 4);

            float z = __expf(part);
            denom += z;
            a0 += z * cx4.x;
            a1 += z * cx4.y;
            a2 += z * cx4.z;
            a3 += z * cx4.w;
        }
        float inv = 1.f / (denom + 1e-16f);
        o.x = a0 * inv + cbias[cb + 0];
        o.y = a1 * inv + cbias[cb + 1];
        o.z = a2 * inv + cbias[cb + 2];
        o.w = a3 * inv + cbias[cb + 3];
        *(float4*)(out + node * HID + cb) = o;

        atomicAdd(&sbn[cb + 0], o.x);             atomicAdd(&sbn[cb + 1], o.y);
        atomicAdd(&sbn[cb + 2], o.z);             atomicAdd(&sbn[cb + 3], o.w);
        atomicAdd(&sbn[256 + cb + 0], o.x * o.x); atomicAdd(&sbn[256 + cb + 1], o.y * o.y);
        atomicAdd(&sbn[256 + cb + 2], o.z * o.z); atomicAdd(&sbn[256 + cb + 3], o.w * o.w);
    }
    __syncthreads();
    atomicAdd(&g_bstats[threadIdx.x], sbn[threadIdx.x]);
    atomicAdd(&g_bstats[threadIdx.x + 256], sbn[threadIdx.x + 256]);
}

// ----------------- MLP BatchNorm accumulation (atomic into g_bstats) --------
__global__ void bn_accum_k(const float* __restrict__ a) {
    int c = threadIdx.x, b = blockIdx.x;       // 128 blocks
    float s = 0.f, q = 0.f;
    for (int r = b; r < NN; r += 128) {
        float v = a[r * 256 + c];
        s += v; q += v * v;
    }
    atomicAdd(&g_bstats[c], s);
    atomicAdd(&g_bstats[256 + c], q);
}

// -------- final 256x3 projection (BN coefs computed in-kernel, fp32) --------
__global__ void proj3_k(const float* __restrict__ h, const float* __restrict__ W,
                        const float* __restrict__ b,
                        const float* __restrict__ gamma, const float* __restrict__ beta,
                        float* __restrict__ out) {
    __shared__ float sscale[HID], sshift[HID];
    {
        int c = threadIdx.x;
        float mu  = g_bstats[c] * INV_NN;
        float var = g_bstats[256 + c] * INV_NN - mu * mu;
        if (var < 0.f) var = 0.f;
        float sc = gamma[c] * rsqrtf(var + 1e-5f);
        sscale[c] = sc;
        sshift[c] = beta[c] - mu * sc;
    }
    __syncthreads();

    int gw = (blockIdx.x * blockDim.x + threadIdx.x) >> 5;
    int lane = threadIdx.x & 31;
    if (gw >= NN) return;
    int cbase = lane * 8;
    const float* hp = h + gw * HID + cbase;
    float4 h0 = *(const float4*)hp;
    float4 h1 = *(const float4*)(hp + 4);
    float4 s0_ = *(const float4*)(sscale + cbase);
    float4 s1_ = *(const float4*)(sscale + cbase + 4);
    float4 f0_ = *(const float4*)(sshift + cbase);
    float4 f1_ = *(const float4*)(sshift + cbase + 4);
    float hv[8];
    hv[0] = fmaxf(h0.x * s0_.x + f0_.x, 0.f);
    hv[1] = fmaxf(h0.y * s0_.y + f0_.y, 0.f);
    hv[2] = fmaxf(h0.z * s0_.z + f0_.z, 0.f);
    hv[3] = fmaxf(h0.w * s0_.w + f0_.w, 0.f);
    hv[4] = fmaxf(h1.x * s1_.x + f1_.x, 0.f);
    hv[5] = fmaxf(h1.y * s1_.y + f1_.y, 0.f);
    hv[6] = fmaxf(h1.z * s1_.z + f1_.z, 0.f);
    hv[7] = fmaxf(h1.w * s1_.w + f1_.w, 0.f);
    float s0 = 0.f, s1 = 0.f, s2 = 0.f;
#pragma unroll
    for (int j = 0; j < 8; j++) {
        int c = cbase + j;
        s0 += hv[j] * W[c * 3 + 0];
        s1 += hv[j] * W[c * 3 + 1];
        s2 += hv[j] * W[c * 3 + 2];
    }
    for (int o = 16; o; o >>= 1) {
        s0 += __shfl_down_sync(0xffffffffu, s0, o);
        s1 += __shfl_down_sync(0xffffffffu, s1, o);
        s2 += __shfl_down_sync(0xffffffffu, s2, o);
    }
    if (lane == 0) {
        out[gw * 3 + 0] = s0 + b[0];
        out[gw * 3 + 1] = s1 + b[1];
        out[gw * 3 + 2] = s2 + b[2];
    }
}

// --------------------------------- launcher ---------------------------------
extern "C" void kernel_launch(void* const* d_in, const int* in_sizes, int n_in,
                              void* d_out, int out_size) {
    const float* x         = (const float*)d_in[0];
    const float* edge_attr = (const float*)d_in[1];
    const int*   edge_idx  = (const int*)  d_in[2];
    const float* lift_W    = (const float*)d_in[3];
    const float* lift_b    = (const float*)d_in[4];
    const float* Wl        = (const float*)d_in[5];
    const float* bl        = (const float*)d_in[6];
    const float* Wr        = (const float*)d_in[7];
    const float* br        = (const float*)d_in[8];
    const float* We        = (const float*)d_in[9];
    const float* att       = (const float*)d_in[10];
    const float* conv_bias = (const float*)d_in[11];
    const float* bn_gamma  = (const float*)d_in[12];
    const float* bn_beta   = (const float*)d_in[13];
    const float* p1_W      = (const float*)d_in[14];
    const float* p1_b      = (const float*)d_in[15];
    const float* pbn1_g    = (const float*)d_in[16];
    const float* pbn1_b    = (const float*)d_in[17];
    const float* p2_W      = (const float*)d_in[18];
    const float* p2_b      = (const float*)d_in[19];
    const float* pbn2_g    = (const float*)d_in[20];
    const float* pbn2_b    = (const float*)d_in[21];
    const float* p3_W      = (const float*)d_in[22];
    const float* p3_b      = (const float*)d_in[23];
    float* outp = (float*)d_out;

    float* p_xl  = nullptr;  cudaGetSymbolAddress((void**)&p_xl,  g_xl);
    float* p_xr  = nullptr;  cudaGetSymbolAddress((void**)&p_xr,  g_xr);
    float* p_out = nullptr;  cudaGetSymbolAddress((void**)&p_out, g_out);

    const int EB = (EE + 255) / 256;              // 625
    dim3 ggrid2(4, MPAD / 128, 2);                // dual GEMM (Wl + Wr)
    dim3 ggrid1(4, MPAD / 128, 1);                // single GEMM
    const int ASB = (MPAD * 64 + 255) / 256;      // asplit blocks

    ea_accum_k<<<64, 256>>>(edge_attr);           // also zeroes g_deg
    ea_norm_k<<<EB, 256>>>(edge_attr, edge_idx);  // also degree histogram

    lift_k<<<NN, 256>>>(x, lift_W, lift_b);       // writes Ahi/Alo directly

    scan_k<<<1, 1024>>>();

    WPtrs wp;
    for (int t = 0; t < TT; t++) {
        wp.p[t]     = Wl + t * HID * HID;
        wp.p[5 + t] = Wr + t * HID * HID;
    }
    wp.p[10] = p1_W;
    wp.p[11] = p2_W;
    scatter_wsplit_k<<<625 + 96, 256>>>(edge_idx, wp);

    for (int t = 0; t < TT; t++) {
        if (t > 0)
            asplit_bn_k<<<ASB, 256>>>(p_out, 1,
                                      bn_gamma + (t - 1) * HID, bn_beta + (t - 1) * HID);
        mma_gemm_k<<<ggrid2, 256>>>(t, bl + t * HID, p_xl,
                                    5 + t, br + t * HID, p_xr);
        gat_edge_k<<<2500, 256>>>(
            p_xl, p_xr, We + t * 9 * HID, att + t * HID, conv_bias + t * HID, p_out);
    }

    // projection MLP
    asplit_bn_k<<<ASB, 256>>>(p_out, 1, bn_gamma + 4 * HID, bn_beta + 4 * HID);
    mma_gemm_k<<<ggrid1, 256>>>(10, p1_b, p_xl, 10, p1_b, p_xl);
    bn_accum_k<<<128, 256>>>(p_xl);

    asplit_bn_k<<<ASB, 256>>>(p_xl, 2, pbn1_g, pbn1_b);
    mma_gemm_k<<<ggrid1, 256>>>(11, p2_b, p_xr, 11, p2_b, p_xr);
    bn_accum_k<<<128, 256>>>(p_xr);

    proj3_k<<<(NN * 32 + 255) / 256, 256>>>(p_xr, p3_W, p3_b, pbn2_g, pbn2_b, outp);
}

// round 15
// speedup vs baseline: 1.1866x; 1.0074x over previous
#include <cuda_runtime.h>
#include <cuda_bf16.h>
#include <math.h>

#define NN 10000
#define EE 160000
#define IND 10
#define HID 256
#define TT 5
#define ODIM 3
#define MPAD 10112            // 79 * 128
#define INV_NN (1.0f / 10000.0f)

// ------------------------- static scratch (no allocation allowed) -----------
__device__ float  g_ea[EE * 12];        // normalized edge attrs (edge order)
__device__ float  g_ea2[EE * 12];       // normalized edge attrs (CSR order)
__device__ float  g_xl[NN * HID];
__device__ float  g_xr[NN * HID];
__device__ float  g_out[NN * HID];      // raw conv output (pre-BN)
__device__ int    g_deg[NN];
__device__ int    g_rowptr[NN + 1];
__device__ int    g_writeptr[NN];
__device__ int    g_src[EE];
__device__ float  g_epart[64 * 18];     // per-block edge-attr stat partials
__device__ float  g_bstats[512];        // fp32 BN stats (atomic target)

// bf16 split operands
__device__ __nv_bfloat16 g_Ahi[MPAD * HID];
__device__ __nv_bfloat16 g_Alo[MPAD * HID];
__device__ __nv_bfloat16 g_Bhi[12 * HID * HID];   // transposed: [slot][n][k]
__device__ __nv_bfloat16 g_Blo[12 * HID * HID];

// ---- edge-attr stat partials (no atomics) + zeroing of g_deg ---------------
__global__ void ea_accum_k(const float* __restrict__ ea) {
    int gi = blockIdx.x * blockDim.x + threadIdx.x;   // 16384 threads
    if (gi < NN) g_deg[gi] = 0;

    float s[9], q[9];
#pragma unroll
    for (int c = 0; c < 9; c++) { s[c] = 0.f; q[c] = 0.f; }
    int stride = gridDim.x * blockDim.x;
    for (int r = gi; r < EE; r += stride) {
#pragma unroll
        for (int c = 0; c < 9; c++) {
            float v = ea[r * 9 + c];
            s[c] += v; q[c] += v * v;
        }
    }
#pragma unroll
    for (int c = 0; c < 9; c++) {
        for (int o = 16; o; o >>= 1) {
            s[c] += __shfl_down_sync(0xffffffffu, s[c], o);
            q[c] += __shfl_down_sync(0xffffffffu, q[c], o);
        }
    }
    __shared__ float warr[8][18];
    int lane = threadIdx.x & 31, wid = threadIdx.x >> 5;
    if (lane == 0) {
#pragma unroll
        for (int c = 0; c < 9; c++) {
            warr[wid][c] = s[c];
            warr[wid][9 + c] = q[c];
        }
    }
    __syncthreads();
    if (threadIdx.x < 18) {
        float acc = 0.f;
#pragma unroll
        for (int w = 0; w < 8; w++) acc += warr[w][threadIdx.x];
        g_epart[blockIdx.x * 18 + threadIdx.x] = acc;
    }
}

// -------- edge-attr normalization + degree histogram ------------------------
__global__ void ea_norm_k(const float* __restrict__ ea, const int* __restrict__ ei) {
    __shared__ float smu[9], sinv[9];
    if (threadIdx.x < 9) {
        float acc = 0.f, acc2 = 0.f;
#pragma unroll 8
        for (int b = 0; b < 64; b++) {
            acc  += g_epart[b * 18 + threadIdx.x];
            acc2 += g_epart[b * 18 + 9 + threadIdx.x];
        }
        float mu  = acc * (1.0f / (float)EE);
        float var = acc2 * (1.0f / (float)EE) - mu * mu;
        if (var < 0.f) var = 0.f;
        smu[threadIdx.x]  = mu;
        sinv[threadIdx.x] = 1.0f / (sqrtf(var) + 1e-8f);
    }
    __syncthreads();
    int r = blockIdx.x * blockDim.x + threadIdx.x;
    if (r >= EE) return;
    atomicAdd(&g_deg[ei[EE + r]], 1);     // degree histogram (deg zeroed earlier)
#pragma unroll
    for (int c = 0; c < 9; c++)
        g_ea[r * 12 + c] = (ea[r * 9 + c] - smu[c]) * sinv[c];
    g_ea[r * 12 + 9]  = 0.f;
    g_ea[r * 12 + 10] = 0.f;
    g_ea[r * 12 + 11] = 0.f;
}

// ------------------- lift fused with bf16 split (layer-0 A) -----------------
__global__ void lift_k(const float* __restrict__ x, const float* __restrict__ W,
                       const float* __restrict__ b) {
    __shared__ float sx[IND];
    int row = blockIdx.x;
    if (threadIdx.x < IND) sx[threadIdx.x] = x[row * IND + threadIdx.x];
    __syncthreads();
    int c = threadIdx.x;
    float s = b[c];
#pragma unroll
    for (int k = 0; k < IND; k++) s += sx[k] * W[k * HID + c];
    s = fmaxf(s, 0.f);
    __nv_bfloat16 h = __float2bfloat16(s);
    g_Ahi[row * HID + c] = h;
    g_Alo[row * HID + c] = __float2bfloat16(s - __bfloat162float(h));
}

// ------------------------------- CSR scan -----------------------------------
__global__ void scan_k() {
    __shared__ int wsum[32];
    __shared__ int carry_s;
    int tid = threadIdx.x;
    int lane = tid & 31, wid = tid >> 5;
    if (tid == 0) { carry_s = 0; g_rowptr[0] = 0; }
    __syncthreads();
    for (int base = 0; base < NN; base += 1024) {
        int i = base + tid;
        int v = (i < NN) ? g_deg[i] : 0;
        int x = v;
#pragma unroll
        for (int o = 1; o < 32; o <<= 1) {
            int t = __shfl_up_sync(0xffffffffu, x, o);
            if (lane >= o) x += t;
        }
        if (lane == 31) wsum[wid] = x;
        __syncthreads();
        if (wid == 0) {
            int y = wsum[lane];
#pragma unroll
            for (int o = 1; o < 32; o <<= 1) {
                int t = __shfl_up_sync(0xffffffffu, y, o);
                if (lane >= o) y += t;
            }
            wsum[lane] = y;
        }
        __syncthreads();
        int incl = x + (wid ? wsum[wid - 1] : 0) + carry_s;
        if (i < NN) { g_rowptr[i + 1] = incl; g_writeptr[i] = incl - v; }
        int total = wsum[31];
        __syncthreads();
        if (tid == 0) carry_s += total;
        __syncthreads();
    }
}

// --------------------- weight split (standalone, early) ---------------------
struct WPtrs { const float* p[12]; };

__global__ void wsplit_k(WPtrs wp) {
    int slot = blockIdx.x >> 3;
    int ny = blockIdx.x & 7;
    int n = ny * 32 + (threadIdx.x >> 3);
    int k0 = (threadIdx.x & 7) * 32;
    const float* W = wp.p[slot];
    __nv_bfloat16* dh = g_Bhi + slot * 65536 + n * 256 + k0;
    __nv_bfloat16* dl = g_Blo + slot * 65536 + n * 256 + k0;
#pragma unroll 8
    for (int k = 0; k < 32; k++) {
        float v = W[(k0 + k) * 256 + n];
        __nv_bfloat16 h = __float2bfloat16(v);
        dh[k] = h;
        dl[k] = __float2bfloat16(v - __bfloat162float(h));
    }
}

// ------------------------------ scatter (CSR build) -------------------------
__global__ void scatter_k(const int* __restrict__ ei) {
    int e = blockIdx.x * blockDim.x + threadIdx.x;
    if (e >= EE) return;
    int d = ei[EE + e];
    int pos = atomicAdd(&g_writeptr[d], 1);
    g_src[pos] = ei[e];
    const float4* s4 = (const float4*)(g_ea + e * 12);
    float4* t4 = (float4*)(g_ea2 + pos * 12);
    t4[0] = s4[0]; t4[1] = s4[1]; t4[2] = s4[2];
}

// ----- A split with in-kernel BN coefs (fp32): act(BN(src)) -> bf16 hi/lo ---
__global__ void asplit_bn_k(const float* __restrict__ src, int act,
                            const float* __restrict__ gamma,
                            const float* __restrict__ beta) {
    __shared__ float sscale[HID], sshift[HID];
    {
        int c = threadIdx.x;
        float mu  = g_bstats[c] * INV_NN;
        float var = g_bstats[256 + c] * INV_NN - mu * mu;
        if (var < 0.f) var = 0.f;
        float sc = gamma[c] * rsqrtf(var + 1e-5f);
        sscale[c] = sc;
        sshift[c] = beta[c] - mu * sc;
    }
    __syncthreads();

    int i0 = blockIdx.x * blockDim.x + threadIdx.x;   // 4 elements each
    if (i0 >= MPAD * 64) return;
    int row = i0 >> 6;
    int col = (i0 & 63) << 2;
    float4 v = make_float4(0.f, 0.f, 0.f, 0.f);
    if (row < NN) {
        v = *(const float4*)(src + row * 256 + col);
        float4 sc = *(const float4*)(sscale + col);
        float4 sh = *(const float4*)(sshift + col);
        v.x = v.x * sc.x + sh.x;
        v.y = v.y * sc.y + sh.y;
        v.z = v.z * sc.z + sh.z;
        v.w = v.w * sc.w + sh.w;
        if (act == 1) {
            v.x = v.x > 0.f ? v.x : expm1f(v.x);
            v.y = v.y > 0.f ? v.y : expm1f(v.y);
            v.z = v.z > 0.f ? v.z : expm1f(v.z);
            v.w = v.w > 0.f ? v.w : expm1f(v.w);
        } else {
            v.x = fmaxf(v.x, 0.f); v.y = fmaxf(v.y, 0.f);
            v.z = fmaxf(v.z, 0.f); v.w = fmaxf(v.w, 0.f);
        }
    }
    __nv_bfloat162 h0, h1, l0, l1;
    h0.x = __float2bfloat16(v.x); h0.y = __float2bfloat16(v.y);
    h1.x = __float2bfloat16(v.z); h1.y = __float2bfloat16(v.w);
    l0.x = __float2bfloat16(v.x - __bfloat162float(h0.x));
    l0.y = __float2bfloat16(v.y - __bfloat162float(h0.y));
    l1.x = __float2bfloat16(v.z - __bfloat162float(h1.x));
    l1.y = __float2bfloat16(v.w - __bfloat162float(h1.y));
    uint2 uh, ul;
    uh.x = *(unsigned*)&h0; uh.y = *(unsigned*)&h1;
    ul.x = *(unsigned*)&l0; ul.y = *(unsigned*)&l1;
    ((uint2*)g_Ahi)[i0] = uh;
    ((uint2*)g_Alo)[i0] = ul;
}

// ---------------- tensor-core GEMM: C = A @ W + bias (bf16 split) -----------
// ROUND-15 CHANGE: occupancy 2 -> 3 CTAs/SM to hide L2 latency on A loads.
__device__ __forceinline__ void mma_bf16(float* c,
    unsigned a0, unsigned a1, unsigned a2, unsigned a3,
    unsigned b0, unsigned b1) {
    asm volatile(
        "mma.sync.aligned.m16n8k16.row.col.f32.bf16.bf16.f32 "
        "{%0,%1,%2,%3}, {%4,%5,%6,%7}, {%8,%9}, {%0,%1,%2,%3};\n"
        : "+f"(c[0]), "+f"(c[1]), "+f"(c[2]), "+f"(c[3])
        : "r"(a0), "r"(a1), "r"(a2), "r"(a3), "r"(b0), "r"(b1));
}

__global__ void __launch_bounds__(256, 3)
mma_gemm_k(int slot0, const float* __restrict__ bias0, float* __restrict__ C0,
           int slot1, const float* __restrict__ bias1, float* __restrict__ C1) {
    if (blockIdx.x == 0 && blockIdx.y == 0 && blockIdx.z == 0) {
        g_bstats[threadIdx.x] = 0.f;
        g_bstats[threadIdx.x + 256] = 0.f;
    }
    const int slot = blockIdx.z ? slot1 : slot0;
    const float* __restrict__ bias = blockIdx.z ? bias1 : bias0;
    float* __restrict__ C = blockIdx.z ? C1 : C0;

    __shared__ __align__(16) __nv_bfloat16 Bs_h[64][136];  // pitch 68 words
    __shared__ __align__(16) __nv_bfloat16 Bs_l[64][136];

    const int w = threadIdx.x >> 5;
    const int lane = threadIdx.x & 31;
    const int g = lane >> 2;
    const int t = lane & 3;
    const int mbase = blockIdx.y << 7;
    const int nb = blockIdx.x << 6;
    const int r0 = mbase + (w << 4) + g;

    const __nv_bfloat16* Bh = g_Bhi + slot * 65536;
    const __nv_bfloat16* Bl = g_Blo + slot * 65536;
    const unsigned* __restrict__ Agh = (const unsigned*)g_Ahi;
    const unsigned* __restrict__ Agl = (const unsigned*)g_Alo;

    float acc[8][4];
#pragma unroll
    for (int j = 0; j < 8; j++)
#pragma unroll
        for (int q = 0; q < 4; q++) acc[j][q] = 0.f;

    for (int kh = 0; kh < 2; kh++) {
        {
            int row = threadIdx.x >> 2;
            int q = threadIdx.x & 3;
            const uint4* sh4 = (const uint4*)(Bh + (nb + row) * 256 + kh * 128 + q * 32);
            const uint4* sl4 = (const uint4*)(Bl + (nb + row) * 256 + kh * 128 + q * 32);
            uint4* dh4 = (uint4*)(&Bs_h[row][q * 32]);
            uint4* dl4 = (uint4*)(&Bs_l[row][q * 32]);
#pragma unroll
            for (int u = 0; u < 4; u++) { dh4[u] = sh4[u]; dl4[u] = sl4[u]; }
        }
        __syncthreads();

        const unsigned* bsh = (const unsigned*)Bs_h;
        const unsigned* bsl = (const unsigned*)Bs_l;
#pragma unroll
        for (int s = 0; s < 8; s++) {
            int kw = kh * 64 + s * 8 + t;
            unsigned ah0 = Agh[r0 * 128 + kw];
            unsigned ah1 = Agh[(r0 + 8) * 128 + kw];
            unsigned ah2 = Agh[r0 * 128 + kw + 4];
            unsigned ah3 = Agh[(r0 + 8) * 128 + kw + 4];
            unsigned al0 = Agl[r0 * 128 + kw];
            unsigned al1 = Agl[(r0 + 8) * 128 + kw];
            unsigned al2 = Agl[r0 * 128 + kw + 4];
            unsigned al3 = Agl[(r0 + 8) * 128 + kw + 4];
#pragma unroll
            for (int j = 0; j < 8; j++) {
                int n = (j << 3) + g;
                int wi = n * 68 + (s << 3) + t;
                unsigned bh0 = bsh[wi], bh1 = bsh[wi + 4];
                unsigned bl0 = bsl[wi], bl1 = bsl[wi + 4];
                mma_bf16(acc[j], ah0, ah1, ah2, ah3, bh0, bh1);
                mma_bf16(acc[j], al0, al1, al2, al3, bh0, bh1);
                mma_bf16(acc[j], ah0, ah1, ah2, ah3, bl0, bl1);
            }
        }
        __syncthreads();
    }

#pragma unroll
    for (int j = 0; j < 8; j++) {
        int c = nb + (j << 3) + (t << 1);
        float2 bv = *(const float2*)(bias + c);
        if (r0 < NN) {
            float2 o; o.x = acc[j][0] + bv.x; o.y = acc[j][1] + bv.y;
            *(float2*)(C + r0 * 256 + c) = o;
        }
        if (r0 + 8 < NN) {
            float2 o; o.x = acc[j][2] + bv.x; o.y = acc[j][3] + bv.y;
            *(float2*)(C + (r0 + 8) * 256 + c) = o;
        }
    }
}

// --------- GATv2 edge pass: plain-exp softmax + fused BN-stat atomics -------
__global__ void gat_edge_k(const float* __restrict__ xl, const float* __restrict__ xr,
                           const float* __restrict__ We_t, const float* __restrict__ att_t,
                           const float* __restrict__ cbias, float* __restrict__ out) {
    __shared__ float sbn[512];
    sbn[threadIdx.x] = 0.f;
    sbn[threadIdx.x + 256] = 0.f;
    __syncthreads();

    int gw = (blockIdx.x * blockDim.x + threadIdx.x) >> 5;
    int lane = threadIdx.x & 31;
    int node = gw >> 1;
    int cb = ((gw & 1) << 7) + (lane << 2);
    bool active = (gw < NN * 2);

    float4 o = make_float4(0.f, 0.f, 0.f, 0.f);
    if (active) {
        float4 wk[9];
#pragma unroll
        for (int k = 0; k < 9; k++) wk[k] = *(const float4*)(We_t + k * HID + cb);
        float4 xr4 = *(const float4*)(xr + node * HID + cb);
        float4 at4 = *(const float4*)(att_t + cb);

        int beg = g_rowptr[node], end = g_rowptr[node + 1];
        float denom = 0.f;
        float a0 = 0.f, a1 = 0.f, a2 = 0.f, a3 = 0.f;

        float4 e0, e1, e2, x4;
        if (beg < end) {
            int s = g_src[beg];
            const float4* eap = (const float4*)(g_ea2 + beg * 12);
            e0 = eap[0]; e1 = eap[1]; e2 = eap[2];
            x4 = *(const float4*)(xl + s * HID + cb);
        }

        for (int pos = beg; pos < end; pos++) {
            float4 ce0 = e0, ce1 = e1, ce2 = e2, cx4 = x4;
            if (pos + 1 < end) {
                int sn = g_src[pos + 1];
                const float4* eap = (const float4*)(g_ea2 + (pos + 1) * 12);
                e0 = eap[0]; e1 = eap[1]; e2 = eap[2];
                x4 = *(const float4*)(xl + sn * HID + cb);
            }

            float xe0 = ce0.x*wk[0].x + ce0.y*wk[1].x + ce0.z*wk[2].x + ce0.w*wk[3].x
                      + ce1.x*wk[4].x + ce1.y*wk[5].x + ce1.z*wk[6].x + ce1.w*wk[7].x + ce2.x*wk[8].x;
            float xe1 = ce0.x*wk[0].y + ce0.y*wk[1].y + ce0.z*wk[2].y + ce0.w*wk[3].y
                      + ce1.x*wk[4].y + ce1.y*wk[5].y + ce1.z*wk[6].y + ce1.w*wk[7].y + ce2.x*wk[8].y;
            float xe2 = ce0.x*wk[0].z + ce0.y*wk[1].z + ce0.z*wk[2].z + ce0.w*wk[3].z
                      + ce1.x*wk[4].z + ce1.y*wk[5].z + ce1.z*wk[6].z + ce1.w*wk[7].z + ce2.x*wk[8].z;
            float xe3 = ce0.x*wk[0].w + ce0.y*wk[1].w + ce0.z*wk[2].w + ce0.w*wk[3].w
                      + ce1.x*wk[4].w + ce1.y*wk[5].w + ce1.z*wk[6].w + ce1.w*wk[7].w + ce2.x*wk[8].w;

            float v0 = cx4.x + xr4.x + xe0; v0 = v0 > 0.f ? v0 : 0.2f * v0;
            float v1 = cx4.y + xr4.y + xe1; v1 = v1 > 0.f ? v1 : 0.2f * v1;
            float v2 = cx4.z + xr4.z + xe2; v2 = v2 > 0.f ? v2 : 0.2f * v2;
            float v3 = cx4.w + xr4.w + xe3; v3 = v3 > 0.f ? v3 : 0.2f * v3;

            float part = v0 * at4.x + v1 * at4.y + v2 * at4.z + v3 * at4.w;
            part += __shfl_xor_sync(0xffffffffu, part, 1);
            part += __shfl_xor_sync(0xffffffffu, part, 2);
            part += __shfl_xor_sync(0xffffffffu, part, 4);

            float z = __expf(part);
            denom += z;
            a0 += z * cx4.x;
            a1 += z * cx4.y;
            a2 += z * cx4.z;
            a3 += z * cx4.w;
        }
        float inv = 1.f / (denom + 1e-16f);
        o.x = a0 * inv + cbias[cb + 0];
        o.y = a1 * inv + cbias[cb + 1];
        o.z = a2 * inv + cbias[cb + 2];
        o.w = a3 * inv + cbias[cb + 3];
        *(float4*)(out + node * HID + cb) = o;

        atomicAdd(&sbn[cb + 0], o.x);             atomicAdd(&sbn[cb + 1], o.y);
        atomicAdd(&sbn[cb + 2], o.z);             atomicAdd(&sbn[cb + 3], o.w);
        atomicAdd(&sbn[256 + cb + 0], o.x * o.x); atomicAdd(&sbn[256 + cb + 1], o.y * o.y);
        atomicAdd(&sbn[256 + cb + 2], o.z * o.z); atomicAdd(&sbn[256 + cb + 3], o.w * o.w);
    }
    __syncthreads();
    atomicAdd(&g_bstats[threadIdx.x], sbn[threadIdx.x]);
    atomicAdd(&g_bstats[threadIdx.x + 256], sbn[threadIdx.x + 256]);
}

// ----------------- MLP BatchNorm accumulation (atomic into g_bstats) --------
__global__ void bn_accum_k(const float* __restrict__ a) {
    int c = threadIdx.x, b = blockIdx.x;       // 128 blocks
    float s = 0.f, q = 0.f;
    for (int r = b; r < NN; r += 128) {
        float v = a[r * 256 + c];
        s += v; q += v * v;
    }
    atomicAdd(&g_bstats[c], s);
    atomicAdd(&g_bstats[256 + c], q);
}

// -------- final 256x3 projection (BN coefs computed in-kernel, fp32) --------
__global__ void proj3_k(const float* __restrict__ h, const float* __restrict__ W,
                        const float* __restrict__ b,
                        const float* __restrict__ gamma, const float* __restrict__ beta,
                        float* __restrict__ out) {
    __shared__ float sscale[HID], sshift[HID];
    {
        int c = threadIdx.x;
        float mu  = g_bstats[c] * INV_NN;
        float var = g_bstats[256 + c] * INV_NN - mu * mu;
        if (var < 0.f) var = 0.f;
        float sc = gamma[c] * rsqrtf(var + 1e-5f);
        sscale[c] = sc;
        sshift[c] = beta[c] - mu * sc;
    }
    __syncthreads();

    int gw = (blockIdx.x * blockDim.x + threadIdx.x) >> 5;
    int lane = threadIdx.x & 31;
    if (gw >= NN) return;
    int cbase = lane * 8;
    const float* hp = h + gw * HID + cbase;
    float4 h0 = *(const float4*)hp;
    float4 h1 = *(const float4*)(hp + 4);
    float4 s0_ = *(const float4*)(sscale + cbase);
    float4 s1_ = *(const float4*)(sscale + cbase + 4);
    float4 f0_ = *(const float4*)(sshift + cbase);
    float4 f1_ = *(const float4*)(sshift + cbase + 4);
    float hv[8];
    hv[0] = fmaxf(h0.x * s0_.x + f0_.x, 0.f);
    hv[1] = fmaxf(h0.y * s0_.y + f0_.y, 0.f);
    hv[2] = fmaxf(h0.z * s0_.z + f0_.z, 0.f);
    hv[3] = fmaxf(h0.w * s0_.w + f0_.w, 0.f);
    hv[4] = fmaxf(h1.x * s1_.x + f1_.x, 0.f);
    hv[5] = fmaxf(h1.y * s1_.y + f1_.y, 0.f);
    hv[6] = fmaxf(h1.z * s1_.z + f1_.z, 0.f);
    hv[7] = fmaxf(h1.w * s1_.w + f1_.w, 0.f);
    float s0 = 0.f, s1 = 0.f, s2 = 0.f;
#pragma unroll
    for (int j = 0; j < 8; j++) {
        int c = cbase + j;
        s0 += hv[j] * W[c * 3 + 0];
        s1 += hv[j] * W[c * 3 + 1];
        s2 += hv[j] * W[c * 3 + 2];
    }
    for (int o = 16; o; o >>= 1) {
        s0 += __shfl_down_sync(0xffffffffu, s0, o);
        s1 += __shfl_down_sync(0xffffffffu, s1, o);
        s2 += __shfl_down_sync(0xffffffffu, s2, o);
    }
    if (lane == 0) {
        out[gw * 3 + 0] = s0 + b[0];
        out[gw * 3 + 1] = s1 + b[1];
        out[gw * 3 + 2] = s2 + b[2];
    }
}

// --------------------------------- launcher ---------------------------------
extern "C" void kernel_launch(void* const* d_in, const int* in_sizes, int n_in,
                              void* d_out, int out_size) {
    const float* x         = (const float*)d_in[0];
    const float* edge_attr = (const float*)d_in[1];
    const int*   edge_idx  = (const int*)  d_in[2];
    const float* lift_W    = (const float*)d_in[3];
    const float* lift_b    = (const float*)d_in[4];
    const float* Wl        = (const float*)d_in[5];
    const float* bl        = (const float*)d_in[6];
    const float* Wr        = (const float*)d_in[7];
    const float* br        = (const float*)d_in[8];
    const float* We        = (const float*)d_in[9];
    const float* att       = (const float*)d_in[10];
    const float* conv_bias = (const float*)d_in[11];
    const float* bn_gamma  = (const float*)d_in[12];
    const float* bn_beta   = (const float*)d_in[13];
    const float* p1_W      = (const float*)d_in[14];
    const float* p1_b      = (const float*)d_in[15];
    const float* pbn1_g    = (const float*)d_in[16];
    const float* pbn1_b    = (const float*)d_in[17];
    const float* p2_W      = (const float*)d_in[18];
    const float* p2_b      = (const float*)d_in[19];
    const float* pbn2_g    = (const float*)d_in[20];
    const float* pbn2_b    = (const float*)d_in[21];
    const float* p3_W      = (const float*)d_in[22];
    const float* p3_b      = (const float*)d_in[23];
    float* outp = (float*)d_out;

    float* p_xl  = nullptr;  cudaGetSymbolAddress((void**)&p_xl,  g_xl);
    float* p_xr  = nullptr;  cudaGetSymbolAddress((void**)&p_xr,  g_xr);
    float* p_out = nullptr;  cudaGetSymbolAddress((void**)&p_out, g_out);

    const int EB = (EE + 255) / 256;              // 625
    dim3 ggrid2(4, MPAD / 128, 2);                // dual GEMM (Wl + Wr)
    dim3 ggrid1(4, MPAD / 128, 1);                // single GEMM
    const int ASB = (MPAD * 64 + 255) / 256;      // asplit blocks

    WPtrs wp;
    for (int t = 0; t < TT; t++) {
        wp.p[t]     = Wl + t * HID * HID;
        wp.p[5 + t] = Wr + t * HID * HID;
    }
    wp.p[10] = p1_W;
    wp.p[11] = p2_W;

    // Reordered so the first mma_gemm_k is launch #4 (ncu captures launch #4).
    lift_k<<<NN, 256>>>(x, lift_W, lift_b);                 // 1
    wsplit_k<<<96, 256>>>(wp);                              // 2
    ea_accum_k<<<64, 256>>>(edge_attr);                     // 3 (zeroes g_deg)
    mma_gemm_k<<<ggrid2, 256>>>(0, bl, p_xl, 5, br, p_xr);  // 4  <- profiled
    ea_norm_k<<<EB, 256>>>(edge_attr, edge_idx);            // 5 (degree histogram)
    scan_k<<<1, 1024>>>();                                  // 6
    scatter_k<<<EB, 256>>>(edge_idx);                       // 7

    for (int t = 0; t < TT; t++) {
        if (t > 0) {
            asplit_bn_k<<<ASB, 256>>>(p_out, 1,
                                      bn_gamma + (t - 1) * HID, bn_beta + (t - 1) * HID);
            mma_gemm_k<<<ggrid2, 256>>>(t, bl + t * HID, p_xl,
                                        5 + t, br + t * HID, p_xr);
        }
        gat_edge_k<<<2500, 256>>>(
            p_xl, p_xr, We + t * 9 * HID, att + t * HID, conv_bias + t * HID, p_out);
    }

    // projection MLP
    asplit_bn_k<<<ASB, 256>>>(p_out, 1, bn_gamma + 4 * HID, bn_beta + 4 * HID);
    mma_gemm_k<<<ggrid1, 256>>>(10, p1_b, p_xl, 10, p1_b, p_xl);
    bn_accum_k<<<128, 256>>>(p_xl);

    asplit_bn_k<<<ASB, 256>>>(p_xl, 2, pbn1_g, pbn1_b);
    mma_gemm_k<<<ggrid1, 256>>>(11, p2_b, p_xr, 11, p2_b, p_xr);
    bn_accum_k<<<128, 256>>>(p_xr);

    proj3_k<<<(NN * 32 + 255) / 256, 256>>>(p_xr, p3_W, p3_b, pbn2_g, pbn2_b, outp);
}